// round 7
// baseline (speedup 1.0000x reference)
#include <cuda_runtime.h>
#include <cuda_fp16.h>
#include <cstdint>

#define BMAX 16384
__device__ float g_xp[BMAX * 512];
__device__ float g_hs[BMAX * 128];
__device__ float g_c2wt[32 * 9 * 64];   // conv2 weights [ic][k][oc]
__device__ float g_d1wt[64 * 9 * 32];   // deconv1 conv-equiv weights [ic][k][oc]

__device__ __forceinline__ float fsig(float x) { return 1.0f / (1.0f + __expf(-x)); }
__device__ __forceinline__ float ftanh(float x) { return 2.0f * fsig(2.0f * x) - 1.0f; }
__device__ __forceinline__ unsigned pack2(float x, float y) {
    __half2 h = __floats2half2_rn(x, y);
    return *reinterpret_cast<unsigned*>(&h);
}
__device__ __forceinline__ void mma16816(float* c, const unsigned* a, unsigned b0, unsigned b1) {
    asm volatile(
        "mma.sync.aligned.m16n8k16.row.col.f32.f16.f16.f32 "
        "{%0,%1,%2,%3},{%4,%5,%6,%7},{%8,%9},{%0,%1,%2,%3};\n"
        : "+f"(c[0]), "+f"(c[1]), "+f"(c[2]), "+f"(c[3])
        : "r"(a[0]), "r"(a[1]), "r"(a[2]), "r"(a[3]), "r"(b0), "r"(b1));
}
__device__ __forceinline__ void fma2(unsigned long long& acc, unsigned long long a, unsigned long long b) {
    asm("fma.rn.f32x2 %0, %1, %2, %0;" : "+l"(acc) : "l"(a), "l"(b));
}
__device__ __forceinline__ unsigned long long pk2(float x) {
    unsigned long long r; asm("mov.b64 %0, {%1,%2};" : "=l"(r) : "f"(x), "f"(x)); return r;
}
__device__ __forceinline__ float2 upk2(unsigned long long v) {
    float2 r; asm("mov.b64 {%0,%1}, %2;" : "=f"(r.x), "=f"(r.y) : "l"(v)); return r;
}
__device__ __forceinline__ uint32_t smem_u32(const void* p) {
    uint32_t a;
    asm("{ .reg .u64 t; cvta.to.shared.u64 t, %1; cvt.u32.u64 %0, t; }" : "=r"(a) : "l"(p));
    return a;
}
__device__ __forceinline__ void cp_async4(uint32_t s, const void* g) {
    asm volatile("cp.async.ca.shared.global [%0], [%1], 4;" :: "r"(s), "l"(g));
}
__device__ __forceinline__ void cp_commit() { asm volatile("cp.async.commit_group;"); }
__device__ __forceinline__ void cp_wait5() { asm volatile("cp.async.wait_group 5;"); }

// ================= weight prep =================
__global__ void prep_kernel(const float* __restrict__ c2w, const float* __restrict__ d1w) {
    int i = blockIdx.x * 256 + threadIdx.x;
    if (i < 18432) {
        int oc = i / 288, r = i % 288, ic = r / 9, k = r % 9;
        g_c2wt[(ic * 9 + k) * 64 + oc] = c2w[i];
        int ic2 = i / 288, r2 = i % 288, oc2 = r2 / 9, kk = r2 % 9;
        g_d1wt[(ic2 * 9 + (8 - kk)) * 32 + oc2] = d1w[i];
    }
}

// ================= encoder + input projection (R5, unchanged) =================
__global__ void __launch_bounds__(128) enc_kernel(
    const float* __restrict__ img, const float* __restrict__ act,
    const float* __restrict__ c1w, const float* __restrict__ c1b,
    const float* __restrict__ c2b,
    const float* __restrict__ encw, const float* __restrict__ encb,
    const float* __restrict__ wih, const float* __restrict__ bih,
    const float* __restrict__ bhh, int B)
{
    __shared__ float s_img[4][76];
    __shared__ float s_x[4][136];
    __shared__ float s_h2[4][1600];
    __shared__ float s_wt[4608];

    int tid = threadIdx.x, lane = tid & 31, w = tid >> 5;
    int gi = blockIdx.x * 4 + w;
    bool valid = gi < B;
    float* s_h1 = s_wt + w * 800;

    if (valid) {
        for (int i = lane; i < 75; i += 32) s_img[w][i] = img[gi * 75 + i];
        if (lane < 8) s_x[w][128 + lane] = act[gi * 8 + lane];
    }
    __syncwarp();

    int pidx[9];
    {
        int y = (lane < 25) ? lane / 5 : 0, x = (lane < 25) ? lane % 5 : 0;
        #pragma unroll
        for (int ky = 0; ky < 3; ky++)
            #pragma unroll
            for (int kx = 0; kx < 3; kx++) {
                int yy = y + ky - 1, xx = x + kx - 1;
                pidx[ky*3+kx] = (yy >= 0 && yy < 5 && xx >= 0 && xx < 5) ? yy*5+xx : -1;
            }
    }

    if (lane < 25) {
        float p1[27];
        #pragma unroll
        for (int ic = 0; ic < 3; ic++)
            #pragma unroll
            for (int j = 0; j < 9; j++)
                p1[ic*9+j] = (pidx[j] >= 0) ? s_img[w][ic*25 + pidx[j]] : 0.f;
        #pragma unroll 4
        for (int oc = 0; oc < 32; oc++) {
            float a = __ldg(&c1b[oc]);
            #pragma unroll
            for (int k = 0; k < 27; k++) a += p1[k] * __ldg(&c1w[oc*27+k]);
            s_h1[oc*25+lane] = fmaxf(a, 0.f);
        }
    }
    __syncwarp();

    if (lane < 25) {
        unsigned long long acc2[32];
        #pragma unroll
        for (int q = 0; q < 32; q++) acc2[q] = 0ull;
        for (int ic = 0; ic < 32; ic++) {
            const float* hp = s_h1 + ic * 25;
            unsigned long long p2[9];
            #pragma unroll
            for (int j = 0; j < 9; j++)
                p2[j] = pk2((pidx[j] >= 0) ? hp[pidx[j]] : 0.f);
            const ulonglong2* wt = reinterpret_cast<const ulonglong2*>(&g_c2wt[ic * 576]);
            #pragma unroll
            for (int k = 0; k < 9; k++) {
                #pragma unroll
                for (int q = 0; q < 16; q++) {
                    ulonglong2 wv = __ldg(&wt[k*16 + q]);
                    fma2(acc2[q*2],   p2[k], wv.x);
                    fma2(acc2[q*2+1], p2[k], wv.y);
                }
            }
        }
        #pragma unroll
        for (int q = 0; q < 32; q++) {
            float2 v = upk2(acc2[q]);
            s_h2[w][(2*q)*25   + lane] = fmaxf(v.x + __ldg(&c2b[2*q]),   0.f);
            s_h2[w][(2*q+1)*25 + lane] = fmaxf(v.y + __ldg(&c2b[2*q+1]), 0.f);
        }
    }
    __syncthreads();

    for (int ot = 0; ot < 4; ot++) {
        float acc = 0.f;
        for (int kt = 0; kt < 13; kt++) {
            int k0 = kt * 128, klen = (kt == 12) ? 64 : 128;
            __syncthreads();
            for (int idx = tid; idx < 32 * klen; idx += 128) {
                int r = idx / klen, k = idx - r * klen;
                s_wt[r*132 + k] = encw[(ot*32 + r)*1600 + k0 + k];
            }
            __syncthreads();
            const float4* wt4 = reinterpret_cast<const float4*>(&s_wt[lane*132]);
            const float4* h4  = reinterpret_cast<const float4*>(&s_h2[w][k0]);
            int n4 = klen >> 2;
            #pragma unroll 8
            for (int q = 0; q < n4; q++) {
                float4 wv = wt4[q], hv = h4[q];
                acc += wv.x*hv.x + wv.y*hv.y + wv.z*hv.z + wv.w*hv.w;
            }
        }
        s_x[w][ot*32 + lane] = acc + __ldg(&encb[ot*32 + lane]);
    }

    for (int ot = 0; ot < 16; ot++) {
        __syncthreads();
        for (int idx = tid; idx < 32 * 136; idx += 128) {
            int r = idx / 136, k = idx - r * 136;
            s_wt[r*144 + k] = wih[(ot*32 + r)*136 + k];
        }
        __syncthreads();
        float acc = 0.f;
        const float4* wt4 = reinterpret_cast<const float4*>(&s_wt[lane*144]);
        const float4* xv4 = reinterpret_cast<const float4*>(&s_x[w][0]);
        #pragma unroll 17
        for (int q = 0; q < 34; q++) {
            float4 wv = wt4[q], xv = xv4[q];
            acc += wv.x*xv.x + wv.y*xv.y + wv.z*xv.z + wv.w*xv.w;
        }
        if (valid) {
            int o = ot*32 + lane;
            g_xp[gi*512 + o] = acc + __ldg(&bih[o]) + __ldg(&bhh[o]);
        }
    }
}

// ================= LSTM: 16 warps, 2 tiles/warp, cp.async xp ring =================
// D is replicated across the 4 lanes of each quad (B carries h in every n
// column), so acc is initialized with xp uniformly and NO gather shuffles are
// needed. Lane tg applies one activation (value spread), one shfl_down(2)
// pairs the two factors.
// lo warp w (<8):  tiles {w (i), 16+w (g)} for h rows [16w,16w+16)  -> s_u
// hi warp w (>=8): tiles {8+hb (f), 24+hb (o)}                      -> c, h
__global__ void __launch_bounds__(512) lstm_kernel(
    const float* __restrict__ whh, float* __restrict__ d_out, int B, int out_size)
{
    __shared__ unsigned hbuf[2][64];
    __shared__ float s_u[128];
    __shared__ float s_xp[8][512];

    int tid = threadIdx.x, lane = tid & 31, w = tid >> 5;
    int gr = lane >> 2, tg = lane & 3;
    bool lo = (w < 8);
    int hb = lo ? w : w - 8;
    int t0 = (lo ? 0 : 8) + hb;     // i or f tile
    int t1 = (lo ? 16 : 24) + hb;   // g or o tile

    unsigned a[2][8][4];
    {
        int tiles[2] = {t0, t1};
        #pragma unroll
        for (int tt = 0; tt < 2; tt++) {
            int m0 = tiles[tt] * 16;
            #pragma unroll
            for (int kt = 0; kt < 8; kt++) {
                int k0 = kt*16, q0 = m0+gr, q1 = m0+8+gr, c0 = k0+tg*2, c1 = c0+8;
                a[tt][kt][0] = pack2(__ldg(&whh[q0*128+c0]), __ldg(&whh[q0*128+c0+1]));
                a[tt][kt][1] = pack2(__ldg(&whh[q1*128+c0]), __ldg(&whh[q1*128+c0+1]));
                a[tt][kt][2] = pack2(__ldg(&whh[q0*128+c1]), __ldg(&whh[q0*128+c1+1]));
                a[tt][kt][3] = pack2(__ldg(&whh[q1*128+c1]), __ldg(&whh[q1*128+c1+1]));
            }
        }
    }
    int r0 = hb*16 + gr, r1 = r0 + 8;                 // h rows this warp serves
    int xo0 = t0*16 + gr, xo1 = xo0 + 8;              // xp rows (gate t0)
    int xo2 = t1*16 + gr, xo3 = xo2 + 8;              // xp rows (gate t1)
    if (tid < 64) hbuf[0][tid] = 0u;

    // prefill xp ring for steps 0..5 (one 4B cp.async per thread per slot)
    #pragma unroll
    for (int d = 0; d < 6; d++) {
        if (d < B) cp_async4(smem_u32(&s_xp[d][tid]), &g_xp[d*512 + tid]);
        cp_commit();
    }
    cp_wait5();
    __syncthreads();

    float cA = 0.f, cB = 0.f;   // hi warps: tg0 row r0, tg1 row r1
    for (int t = 0; t < B; t++) {
        const unsigned* h2p = hbuf[t & 1];
        const float* xp = s_xp[t & 7];
        float acc0[4], acc1[4];
        acc0[0] = xp[xo0]; acc0[1] = 0.f; acc0[2] = xp[xo1]; acc0[3] = 0.f;
        acc1[0] = xp[xo2]; acc1[1] = 0.f; acc1[2] = xp[xo3]; acc1[3] = 0.f;
        #pragma unroll
        for (int kt = 0; kt < 8; kt++) {
            unsigned b0 = h2p[kt*8 + tg], b1 = h2p[kt*8 + 4 + tg];
            mma16816(acc0, a[0][kt], b0, b1);
            mma16816(acc1, a[1][kt], b0, b1);
        }
        // value spread: tg0 -> gate0 rowA, tg1 -> gate0 rowB, tg2 -> gate1 rowA, tg3 -> gate1 rowB
        float pre = (tg==0) ? acc0[0] : (tg==1) ? acc0[2] : (tg==2) ? acc1[0] : acc1[2];
        float val;
        if (lo) {
            bool isg = (tg >= 2);                     // gate1 = g (tanh)
            float v = fsig(isg ? 2.f*pre : pre);
            val = isg ? fmaf(2.f, v, -1.f) : v;       // sig(i) or tanh(g)
            float part = __shfl_down_sync(0xffffffffu, val, 2);   // tg0<-tg2, tg1<-tg3
            if (tg == 0) s_u[r0] = val * part;        // sig(i)*tanh(g)
            else if (tg == 1) s_u[r1] = val * part;
        } else {
            val = fsig(pre);                          // tg0:fA tg1:fB tg2:oA tg3:oB
        }
        __syncthreads();                              // s_u ready
        if (!lo) {
            float og = __shfl_down_sync(0xffffffffu, val, 2);     // tg0:oA tg1:oB
            int r = (tg == 1) ? r1 : r0;
            float u = s_u[r];
            float cc = (tg == 1) ? cB : cA;
            cc = fmaf(val, cc, u);
            float h = og * ftanh(cc);
            if (tg == 0) cA = cc; else if (tg == 1) cB = cc;
            if (tg < 2) {
                __half* hn = reinterpret_cast<__half*>(hbuf[(t+1) & 1]);
                hn[r] = __float2half_rn(h);
                g_hs[t*128 + r] = h;
                if (t == B - 1) {
                    d_out[out_size - 256 + r] = h;
                    d_out[out_size - 128 + r] = cc;
                }
            }
        }
        int tf = t + 6;
        if (tf < B) cp_async4(smem_u32(&s_xp[tf & 7][tid]), &g_xp[tf*512 + tid]);
        cp_commit();
        cp_wait5();
        __syncthreads();                              // hbuf + xp slot ready
    }
}

// ================= decoder (R5, unchanged) =================
__global__ void __launch_bounds__(128) dec_kernel(
    const float* __restrict__ decw, const float* __restrict__ decb,
    const float* __restrict__ d1b,
    const float* __restrict__ d2w, const float* __restrict__ d2b,
    float* __restrict__ out, int B)
{
    __shared__ float s_hs[4][128];
    __shared__ float s_d[4][1600];
    __shared__ float s_wt[4224];
    __shared__ float s_w2f[864];

    int tid = threadIdx.x, lane = tid & 31, w = tid >> 5;
    int gi = blockIdx.x * 4 + w;
    bool valid = gi < B;

    for (int i = tid; i < 864; i += 128) {
        int ic = i / 27, rem = i % 27, oc = rem / 9, k = rem % 9;
        s_w2f[i] = d2w[(ic*3 + oc)*9 + (8 - k)];
    }
    if (valid)
        for (int i = lane; i < 128; i += 32) s_hs[w][i] = g_hs[gi*128 + i];

    for (int ot = 0; ot < 50; ot++) {
        __syncthreads();
        for (int idx = tid; idx < 4096; idx += 128) {
            int r = idx >> 7, k = idx & 127;
            s_wt[r*132 + k] = decw[(ot*32 + r)*128 + k];
        }
        __syncthreads();
        float acc = 0.f;
        const float4* wt4 = reinterpret_cast<const float4*>(&s_wt[lane*132]);
        const float4* h4  = reinterpret_cast<const float4*>(&s_hs[w][0]);
        #pragma unroll 8
        for (int q = 0; q < 32; q++) {
            float4 wv = wt4[q], hv = h4[q];
            acc += wv.x*hv.x + wv.y*hv.y + wv.z*hv.z + wv.w*hv.w;
        }
        s_d[w][ot*32 + lane] = acc + __ldg(&decb[ot*32 + lane]);
    }
    __syncthreads();

    float* s_h1 = s_wt + w * 800;
    int pidx[9];
    {
        int y = (lane < 25) ? lane / 5 : 0, x = (lane < 25) ? lane % 5 : 0;
        #pragma unroll
        for (int ky = 0; ky < 3; ky++)
            #pragma unroll
            for (int kx = 0; kx < 3; kx++) {
                int yy = y + ky - 1, xx = x + kx - 1;
                pidx[ky*3+kx] = (yy >= 0 && yy < 5 && xx >= 0 && xx < 5) ? yy*5+xx : -1;
            }
    }

    if (lane < 25) {
        unsigned long long acc2[16];
        #pragma unroll
        for (int q = 0; q < 16; q++) acc2[q] = 0ull;
        for (int ic = 0; ic < 64; ic++) {
            const float* dp = &s_d[w][ic * 25];
            unsigned long long p2[9];
            #pragma unroll
            for (int j = 0; j < 9; j++)
                p2[j] = pk2((pidx[j] >= 0) ? dp[pidx[j]] : 0.f);
            const ulonglong2* wt = reinterpret_cast<const ulonglong2*>(&g_d1wt[ic * 288]);
            #pragma unroll
            for (int k = 0; k < 9; k++) {
                #pragma unroll
                for (int q = 0; q < 8; q++) {
                    ulonglong2 wv = __ldg(&wt[k*8 + q]);
                    fma2(acc2[q*2],   p2[k], wv.x);
                    fma2(acc2[q*2+1], p2[k], wv.y);
                }
            }
        }
        #pragma unroll
        for (int q = 0; q < 16; q++) {
            float2 v = upk2(acc2[q]);
            s_h1[(2*q)*25   + lane] = fmaxf(v.x + __ldg(&d1b[2*q]),   0.f);
            s_h1[(2*q+1)*25 + lane] = fmaxf(v.y + __ldg(&d1b[2*q+1]), 0.f);
        }
    }
    __syncwarp();

    if (valid && lane < 25) {
        float acc[3] = {__ldg(&d2b[0]), __ldg(&d2b[1]), __ldg(&d2b[2])};
        for (int ic = 0; ic < 32; ic++) {
            float p[9];
            #pragma unroll
            for (int j = 0; j < 9; j++)
                p[j] = (pidx[j] >= 0) ? s_h1[ic*25 + pidx[j]] : 0.f;
            #pragma unroll
            for (int oc = 0; oc < 3; oc++) {
                float a = acc[oc];
                #pragma unroll
                for (int k = 0; k < 9; k++) a += p[k] * s_w2f[ic*27 + oc*9 + k];
                acc[oc] = a;
            }
        }
        #pragma unroll
        for (int oc = 0; oc < 3; oc++)
            out[gi*75 + oc*25 + lane] = fsig(acc[oc]);
    }
}

extern "C" void kernel_launch(void* const* d_in, const int* in_sizes, int n_in,
                              void* d_out, int out_size)
{
    const float* img   = (const float*)d_in[0];
    const float* act   = (const float*)d_in[1];
    const float* c1w   = (const float*)d_in[2];
    const float* c1b   = (const float*)d_in[3];
    const float* c2w   = (const float*)d_in[4];
    const float* c2b   = (const float*)d_in[5];
    const float* encw  = (const float*)d_in[6];
    const float* encb  = (const float*)d_in[7];
    const float* wih   = (const float*)d_in[8];
    const float* whh   = (const float*)d_in[9];
    const float* bih   = (const float*)d_in[10];
    const float* bhh   = (const float*)d_in[11];
    const float* decw  = (const float*)d_in[12];
    const float* decb  = (const float*)d_in[13];
    const float* d1w   = (const float*)d_in[14];
    const float* d1b   = (const float*)d_in[15];
    const float* d2w   = (const float*)d_in[16];
    const float* d2b   = (const float*)d_in[17];
    float* out = (float*)d_out;

    int B = in_sizes[0] / 75;
    int blocks = (B + 3) / 4;

    prep_kernel<<<72, 256>>>(c2w, d1w);
    enc_kernel<<<blocks, 128>>>(img, act, c1w, c1b, c2b, encw, encb, wih, bih, bhh, B);
    lstm_kernel<<<1, 512>>>(whh, out, B, out_size);
    dec_kernel<<<blocks, 128>>>(decw, decb, d1b, d2w, d2b, out, B);
}

// round 8
// speedup vs baseline: 1.0177x; 1.0177x over previous
#include <cuda_runtime.h>
#include <cuda_fp16.h>
#include <cstdint>

#define BMAX 16384
__device__ float g_xp[BMAX * 512];
__device__ float g_hs[BMAX * 128];
__device__ float g_c2wt[32 * 9 * 64];   // conv2 weights [ic][k][oc]
__device__ float g_d1wt[64 * 9 * 32];   // deconv1 conv-equiv weights [ic][k][oc]

__device__ __forceinline__ float fsig(float x) { return 1.0f / (1.0f + __expf(-x)); }
__device__ __forceinline__ float ftanh(float x) { return 2.0f * fsig(2.0f * x) - 1.0f; }
__device__ __forceinline__ unsigned pack2(float x, float y) {
    __half2 h = __floats2half2_rn(x, y);
    return *reinterpret_cast<unsigned*>(&h);
}
__device__ __forceinline__ void mma16816(float* c, const unsigned* a, unsigned b0, unsigned b1) {
    asm volatile(
        "mma.sync.aligned.m16n8k16.row.col.f32.f16.f16.f32 "
        "{%0,%1,%2,%3},{%4,%5,%6,%7},{%8,%9},{%0,%1,%2,%3};\n"
        : "+f"(c[0]), "+f"(c[1]), "+f"(c[2]), "+f"(c[3])
        : "r"(a[0]), "r"(a[1]), "r"(a[2]), "r"(a[3]), "r"(b0), "r"(b1));
}
__device__ __forceinline__ void fma2(unsigned long long& acc, unsigned long long a, unsigned long long b) {
    asm("fma.rn.f32x2 %0, %1, %2, %0;" : "+l"(acc) : "l"(a), "l"(b));
}
__device__ __forceinline__ unsigned long long pk2(float x) {
    unsigned long long r; asm("mov.b64 %0, {%1,%2};" : "=l"(r) : "f"(x), "f"(x)); return r;
}
__device__ __forceinline__ float2 upk2(unsigned long long v) {
    float2 r; asm("mov.b64 {%0,%1}, %2;" : "=f"(r.x), "=f"(r.y) : "l"(v)); return r;
}

// ================= weight prep =================
__global__ void prep_kernel(const float* __restrict__ c2w, const float* __restrict__ d1w) {
    int i = blockIdx.x * 256 + threadIdx.x;
    if (i < 18432) {
        int oc = i / 288, r = i % 288, ic = r / 9, k = r % 9;
        g_c2wt[(ic * 9 + k) * 64 + oc] = c2w[i];
        int ic2 = i / 288, r2 = i % 288, oc2 = r2 / 9, kk = r2 % 9;
        g_d1wt[(ic2 * 9 + (8 - kk)) * 32 + oc2] = d1w[i];
    }
}

// ================= encoder + input projection (R5, unchanged) =================
__global__ void __launch_bounds__(128) enc_kernel(
    const float* __restrict__ img, const float* __restrict__ act,
    const float* __restrict__ c1w, const float* __restrict__ c1b,
    const float* __restrict__ c2b,
    const float* __restrict__ encw, const float* __restrict__ encb,
    const float* __restrict__ wih, const float* __restrict__ bih,
    const float* __restrict__ bhh, int B)
{
    __shared__ float s_img[4][76];
    __shared__ float s_x[4][136];
    __shared__ float s_h2[4][1600];
    __shared__ float s_wt[4608];

    int tid = threadIdx.x, lane = tid & 31, w = tid >> 5;
    int gi = blockIdx.x * 4 + w;
    bool valid = gi < B;
    float* s_h1 = s_wt + w * 800;

    if (valid) {
        for (int i = lane; i < 75; i += 32) s_img[w][i] = img[gi * 75 + i];
        if (lane < 8) s_x[w][128 + lane] = act[gi * 8 + lane];
    }
    __syncwarp();

    int pidx[9];
    {
        int y = (lane < 25) ? lane / 5 : 0, x = (lane < 25) ? lane % 5 : 0;
        #pragma unroll
        for (int ky = 0; ky < 3; ky++)
            #pragma unroll
            for (int kx = 0; kx < 3; kx++) {
                int yy = y + ky - 1, xx = x + kx - 1;
                pidx[ky*3+kx] = (yy >= 0 && yy < 5 && xx >= 0 && xx < 5) ? yy*5+xx : -1;
            }
    }

    if (lane < 25) {
        float p1[27];
        #pragma unroll
        for (int ic = 0; ic < 3; ic++)
            #pragma unroll
            for (int j = 0; j < 9; j++)
                p1[ic*9+j] = (pidx[j] >= 0) ? s_img[w][ic*25 + pidx[j]] : 0.f;
        #pragma unroll 4
        for (int oc = 0; oc < 32; oc++) {
            float a = __ldg(&c1b[oc]);
            #pragma unroll
            for (int k = 0; k < 27; k++) a += p1[k] * __ldg(&c1w[oc*27+k]);
            s_h1[oc*25+lane] = fmaxf(a, 0.f);
        }
    }
    __syncwarp();

    if (lane < 25) {
        unsigned long long acc2[32];
        #pragma unroll
        for (int q = 0; q < 32; q++) acc2[q] = 0ull;
        for (int ic = 0; ic < 32; ic++) {
            const float* hp = s_h1 + ic * 25;
            unsigned long long p2[9];
            #pragma unroll
            for (int j = 0; j < 9; j++)
                p2[j] = pk2((pidx[j] >= 0) ? hp[pidx[j]] : 0.f);
            const ulonglong2* wt = reinterpret_cast<const ulonglong2*>(&g_c2wt[ic * 576]);
            #pragma unroll
            for (int k = 0; k < 9; k++) {
                #pragma unroll
                for (int q = 0; q < 16; q++) {
                    ulonglong2 wv = __ldg(&wt[k*16 + q]);
                    fma2(acc2[q*2],   p2[k], wv.x);
                    fma2(acc2[q*2+1], p2[k], wv.y);
                }
            }
        }
        #pragma unroll
        for (int q = 0; q < 32; q++) {
            float2 v = upk2(acc2[q]);
            s_h2[w][(2*q)*25   + lane] = fmaxf(v.x + __ldg(&c2b[2*q]),   0.f);
            s_h2[w][(2*q+1)*25 + lane] = fmaxf(v.y + __ldg(&c2b[2*q+1]), 0.f);
        }
    }
    __syncthreads();

    for (int ot = 0; ot < 4; ot++) {
        float acc = 0.f;
        for (int kt = 0; kt < 13; kt++) {
            int k0 = kt * 128, klen = (kt == 12) ? 64 : 128;
            __syncthreads();
            for (int idx = tid; idx < 32 * klen; idx += 128) {
                int r = idx / klen, k = idx - r * klen;
                s_wt[r*132 + k] = encw[(ot*32 + r)*1600 + k0 + k];
            }
            __syncthreads();
            const float4* wt4 = reinterpret_cast<const float4*>(&s_wt[lane*132]);
            const float4* h4  = reinterpret_cast<const float4*>(&s_h2[w][k0]);
            int n4 = klen >> 2;
            #pragma unroll 8
            for (int q = 0; q < n4; q++) {
                float4 wv = wt4[q], hv = h4[q];
                acc += wv.x*hv.x + wv.y*hv.y + wv.z*hv.z + wv.w*hv.w;
            }
        }
        s_x[w][ot*32 + lane] = acc + __ldg(&encb[ot*32 + lane]);
    }

    for (int ot = 0; ot < 16; ot++) {
        __syncthreads();
        for (int idx = tid; idx < 32 * 136; idx += 128) {
            int r = idx / 136, k = idx - r * 136;
            s_wt[r*144 + k] = wih[(ot*32 + r)*136 + k];
        }
        __syncthreads();
        float acc = 0.f;
        const float4* wt4 = reinterpret_cast<const float4*>(&s_wt[lane*144]);
        const float4* xv4 = reinterpret_cast<const float4*>(&s_x[w][0]);
        #pragma unroll 17
        for (int q = 0; q < 34; q++) {
            float4 wv = wt4[q], xv = xv4[q];
            acc += wv.x*xv.x + wv.y*xv.y + wv.z*xv.z + wv.w*xv.w;
        }
        if (valid) {
            int o = ot*32 + lane;
            g_xp[gi*512 + o] = acc + __ldg(&bih[o]) + __ldg(&bhh[o]);
        }
    }
}

// ================= LSTM: 16 warps, 2 tiles/warp, LDG prefetch-2 =================
// D replicated across lane quads (B carries h in every n column): no gather
// shuffles. Each lane adds its single xp scalar post-select, applies one
// activation; one shfl_down(2) pairs factors.
// lo warp w (<8):  tiles {w (i), 16+w (g)} for h rows [16w,16w+16)  -> s_u
// hi warp w (>=8): tiles {8+hb (f), 24+hb (o)}                      -> c, h
__global__ void __launch_bounds__(512) lstm_kernel(
    const float* __restrict__ whh, float* __restrict__ d_out, int B, int out_size)
{
    __shared__ unsigned hbuf[2][64];
    __shared__ float s_u[128];

    int tid = threadIdx.x, lane = tid & 31, w = tid >> 5;
    int gr = lane >> 2, tg = lane & 3;
    bool lo = (w < 8);
    int hb = lo ? w : w - 8;
    int t0 = (lo ? 0 : 8) + hb;     // i or f tile
    int t1 = (lo ? 16 : 24) + hb;   // g or o tile

    unsigned a[2][8][4];
    {
        int tiles[2] = {t0, t1};
        #pragma unroll
        for (int tt = 0; tt < 2; tt++) {
            int m0 = tiles[tt] * 16;
            #pragma unroll
            for (int kt = 0; kt < 8; kt++) {
                int k0 = kt*16, q0 = m0+gr, q1 = m0+8+gr, c0 = k0+tg*2, c1 = c0+8;
                a[tt][kt][0] = pack2(__ldg(&whh[q0*128+c0]), __ldg(&whh[q0*128+c0+1]));
                a[tt][kt][1] = pack2(__ldg(&whh[q1*128+c0]), __ldg(&whh[q1*128+c0+1]));
                a[tt][kt][2] = pack2(__ldg(&whh[q0*128+c1]), __ldg(&whh[q0*128+c1+1]));
                a[tt][kt][3] = pack2(__ldg(&whh[q1*128+c1]), __ldg(&whh[q1*128+c1+1]));
            }
        }
    }
    int r0 = hb*16 + gr, r1 = r0 + 8;   // h rows this warp serves
    // single xp element this lane needs: (gate tile, row) by tg
    int xsel = (tg == 0) ? t0*16 + gr
             : (tg == 1) ? t0*16 + 8 + gr
             : (tg == 2) ? t1*16 + gr
                         : t1*16 + 8 + gr;
    if (tid < 64) hbuf[0][tid] = 0u;

    // register prefetch pipeline, distance 2
    float xp0 = __ldg(&g_xp[xsel]);
    float xp1 = (B > 1) ? __ldg(&g_xp[512 + xsel]) : 0.f;
    __syncthreads();

    float cA = 0.f, cB = 0.f;   // hi warps: tg0 row r0, tg1 row r1
    for (int t = 0; t < B; t++) {
        const unsigned* h2p = hbuf[t & 1];
        float acc0[4] = {0.f, 0.f, 0.f, 0.f};
        float acc1[4] = {0.f, 0.f, 0.f, 0.f};
        #pragma unroll
        for (int kt = 0; kt < 8; kt++) {
            unsigned b0 = h2p[kt*8 + tg], b1 = h2p[kt*8 + 4 + tg];
            mma16816(acc0, a[0][kt], b0, b1);
            mma16816(acc1, a[1][kt], b0, b1);
        }
        // value spread: tg0 -> gate0 rowA, tg1 -> gate0 rowB, tg2 -> gate1 rowA, tg3 -> gate1 rowB
        float pre = ((tg==0) ? acc0[0] : (tg==1) ? acc0[2] : (tg==2) ? acc1[0] : acc1[2]) + xp0;
        // slide xp pipeline, prefetch t+2
        xp0 = xp1;
        if (t + 2 < B) xp1 = __ldg(&g_xp[(t+2)*512 + xsel]);

        float val;
        if (lo) {
            bool isg = (tg >= 2);                     // gate1 = g (tanh)
            float v = fsig(isg ? 2.f*pre : pre);
            val = isg ? fmaf(2.f, v, -1.f) : v;       // sig(i) or tanh(g)
            float part = __shfl_down_sync(0xffffffffu, val, 2);   // tg0<-tg2, tg1<-tg3
            if (tg == 0) s_u[r0] = val * part;        // sig(i)*tanh(g)
            else if (tg == 1) s_u[r1] = val * part;
        } else {
            val = fsig(pre);                          // tg0:fA tg1:fB tg2:oA tg3:oB
        }
        __syncthreads();                              // s_u ready
        if (!lo) {
            float og = __shfl_down_sync(0xffffffffu, val, 2);     // tg0:oA tg1:oB
            int r = (tg == 1) ? r1 : r0;
            float u = s_u[r];
            float cc = (tg == 1) ? cB : cA;
            cc = fmaf(val, cc, u);
            float h = og * ftanh(cc);
            if (tg == 0) cA = cc; else if (tg == 1) cB = cc;
            if (tg < 2) {
                __half* hn = reinterpret_cast<__half*>(hbuf[(t+1) & 1]);
                hn[r] = __float2half_rn(h);
                g_hs[t*128 + r] = h;
                if (t == B - 1) {
                    d_out[out_size - 256 + r] = h;
                    d_out[out_size - 128 + r] = cc;
                }
            }
        }
        __syncthreads();                              // hbuf ready
    }
}

// ================= decoder (R5, unchanged) =================
__global__ void __launch_bounds__(128) dec_kernel(
    const float* __restrict__ decw, const float* __restrict__ decb,
    const float* __restrict__ d1b,
    const float* __restrict__ d2w, const float* __restrict__ d2b,
    float* __restrict__ out, int B)
{
    __shared__ float s_hs[4][128];
    __shared__ float s_d[4][1600];
    __shared__ float s_wt[4224];
    __shared__ float s_w2f[864];

    int tid = threadIdx.x, lane = tid & 31, w = tid >> 5;
    int gi = blockIdx.x * 4 + w;
    bool valid = gi < B;

    for (int i = tid; i < 864; i += 128) {
        int ic = i / 27, rem = i % 27, oc = rem / 9, k = rem % 9;
        s_w2f[i] = d2w[(ic*3 + oc)*9 + (8 - k)];
    }
    if (valid)
        for (int i = lane; i < 128; i += 32) s_hs[w][i] = g_hs[gi*128 + i];

    for (int ot = 0; ot < 50; ot++) {
        __syncthreads();
        for (int idx = tid; idx < 4096; idx += 128) {
            int r = idx >> 7, k = idx & 127;
            s_wt[r*132 + k] = decw[(ot*32 + r)*128 + k];
        }
        __syncthreads();
        float acc = 0.f;
        const float4* wt4 = reinterpret_cast<const float4*>(&s_wt[lane*132]);
        const float4* h4  = reinterpret_cast<const float4*>(&s_hs[w][0]);
        #pragma unroll 8
        for (int q = 0; q < 32; q++) {
            float4 wv = wt4[q], hv = h4[q];
            acc += wv.x*hv.x + wv.y*hv.y + wv.z*hv.z + wv.w*hv.w;
        }
        s_d[w][ot*32 + lane] = acc + __ldg(&decb[ot*32 + lane]);
    }
    __syncthreads();

    float* s_h1 = s_wt + w * 800;
    int pidx[9];
    {
        int y = (lane < 25) ? lane / 5 : 0, x = (lane < 25) ? lane % 5 : 0;
        #pragma unroll
        for (int ky = 0; ky < 3; ky++)
            #pragma unroll
            for (int kx = 0; kx < 3; kx++) {
                int yy = y + ky - 1, xx = x + kx - 1;
                pidx[ky*3+kx] = (yy >= 0 && yy < 5 && xx >= 0 && xx < 5) ? yy*5+xx : -1;
            }
    }

    if (lane < 25) {
        unsigned long long acc2[16];
        #pragma unroll
        for (int q = 0; q < 16; q++) acc2[q] = 0ull;
        for (int ic = 0; ic < 64; ic++) {
            const float* dp = &s_d[w][ic * 25];
            unsigned long long p2[9];
            #pragma unroll
            for (int j = 0; j < 9; j++)
                p2[j] = pk2((pidx[j] >= 0) ? dp[pidx[j]] : 0.f);
            const ulonglong2* wt = reinterpret_cast<const ulonglong2*>(&g_d1wt[ic * 288]);
            #pragma unroll
            for (int k = 0; k < 9; k++) {
                #pragma unroll
                for (int q = 0; q < 8; q++) {
                    ulonglong2 wv = __ldg(&wt[k*8 + q]);
                    fma2(acc2[q*2],   p2[k], wv.x);
                    fma2(acc2[q*2+1], p2[k], wv.y);
                }
            }
        }
        #pragma unroll
        for (int q = 0; q < 16; q++) {
            float2 v = upk2(acc2[q]);
            s_h1[(2*q)*25   + lane] = fmaxf(v.x + __ldg(&d1b[2*q]),   0.f);
            s_h1[(2*q+1)*25 + lane] = fmaxf(v.y + __ldg(&d1b[2*q+1]), 0.f);
        }
    }
    __syncwarp();

    if (valid && lane < 25) {
        float acc[3] = {__ldg(&d2b[0]), __ldg(&d2b[1]), __ldg(&d2b[2])};
        for (int ic = 0; ic < 32; ic++) {
            float p[9];
            #pragma unroll
            for (int j = 0; j < 9; j++)
                p[j] = (pidx[j] >= 0) ? s_h1[ic*25 + pidx[j]] : 0.f;
            #pragma unroll
            for (int oc = 0; oc < 3; oc++) {
                float a = acc[oc];
                #pragma unroll
                for (int k = 0; k < 9; k++) a += p[k] * s_w2f[ic*27 + oc*9 + k];
                acc[oc] = a;
            }
        }
        #pragma unroll
        for (int oc = 0; oc < 3; oc++)
            out[gi*75 + oc*25 + lane] = fsig(acc[oc]);
    }
}

extern "C" void kernel_launch(void* const* d_in, const int* in_sizes, int n_in,
                              void* d_out, int out_size)
{
    const float* img   = (const float*)d_in[0];
    const float* act   = (const float*)d_in[1];
    const float* c1w   = (const float*)d_in[2];
    const float* c1b   = (const float*)d_in[3];
    const float* c2w   = (const float*)d_in[4];
    const float* c2b   = (const float*)d_in[5];
    const float* encw  = (const float*)d_in[6];
    const float* encb  = (const float*)d_in[7];
    const float* wih   = (const float*)d_in[8];
    const float* whh   = (const float*)d_in[9];
    const float* bih   = (const float*)d_in[10];
    const float* bhh   = (const float*)d_in[11];
    const float* decw  = (const float*)d_in[12];
    const float* decb  = (const float*)d_in[13];
    const float* d1w   = (const float*)d_in[14];
    const float* d1b   = (const float*)d_in[15];
    const float* d2w   = (const float*)d_in[16];
    const float* d2b   = (const float*)d_in[17];
    float* out = (float*)d_out;

    int B = in_sizes[0] / 75;
    int blocks = (B + 3) / 4;

    prep_kernel<<<72, 256>>>(c2w, d1w);
    enc_kernel<<<blocks, 128>>>(img, act, c1w, c1b, c2b, encw, encb, wih, bih, bhh, B);
    lstm_kernel<<<1, 512>>>(whh, out, B, out_size);
    dec_kernel<<<blocks, 128>>>(decw, decb, d1b, d2w, d2b, out, B);
}

// round 9
// speedup vs baseline: 1.2975x; 1.2749x over previous
#include <cuda_runtime.h>
#include <cuda_fp16.h>
#include <cstdint>

#define BMAX 16384
__device__ float g_xp[BMAX * 512];
__device__ float g_hs[BMAX * 128];
__device__ float g_c2wt[32 * 9 * 64];   // conv2 weights [ic][k][oc]
__device__ float g_d1wt[64 * 9 * 32];   // deconv1 conv-equiv weights [ic][k][oc]

__device__ __forceinline__ float fsig(float x) { return 1.0f / (1.0f + __expf(-x)); }
__device__ __forceinline__ float ftanh(float x) { return 2.0f * fsig(2.0f * x) - 1.0f; }
__device__ __forceinline__ void fma2(unsigned long long& acc, unsigned long long a, unsigned long long b) {
    asm("fma.rn.f32x2 %0, %1, %2, %0;" : "+l"(acc) : "l"(a), "l"(b));
}
__device__ __forceinline__ unsigned long long pk2(float x) {
    unsigned long long r; asm("mov.b64 %0, {%1,%2};" : "=l"(r) : "f"(x), "f"(x)); return r;
}
__device__ __forceinline__ float2 upk2(unsigned long long v) {
    float2 r; asm("mov.b64 {%0,%1}, %2;" : "=f"(r.x), "=f"(r.y) : "l"(v)); return r;
}
__device__ __forceinline__ __half2 u2h2(unsigned u) {
    __half2 h; *reinterpret_cast<unsigned*>(&h) = u; return h;
}

// ================= weight prep =================
__global__ void prep_kernel(const float* __restrict__ c2w, const float* __restrict__ d1w) {
    int i = blockIdx.x * 256 + threadIdx.x;
    if (i < 18432) {
        int oc = i / 288, r = i % 288, ic = r / 9, k = r % 9;
        g_c2wt[(ic * 9 + k) * 64 + oc] = c2w[i];
        int ic2 = i / 288, r2 = i % 288, oc2 = r2 / 9, kk = r2 % 9;
        g_d1wt[(ic2 * 9 + (8 - kk)) * 32 + oc2] = d1w[i];
    }
}

// ================= encoder + input projection (unchanged) =================
__global__ void __launch_bounds__(128) enc_kernel(
    const float* __restrict__ img, const float* __restrict__ act,
    const float* __restrict__ c1w, const float* __restrict__ c1b,
    const float* __restrict__ c2b,
    const float* __restrict__ encw, const float* __restrict__ encb,
    const float* __restrict__ wih, const float* __restrict__ bih,
    const float* __restrict__ bhh, int B)
{
    __shared__ float s_img[4][76];
    __shared__ float s_x[4][136];
    __shared__ float s_h2[4][1600];
    __shared__ float s_wt[4608];

    int tid = threadIdx.x, lane = tid & 31, w = tid >> 5;
    int gi = blockIdx.x * 4 + w;
    bool valid = gi < B;
    float* s_h1 = s_wt + w * 800;

    if (valid) {
        for (int i = lane; i < 75; i += 32) s_img[w][i] = img[gi * 75 + i];
        if (lane < 8) s_x[w][128 + lane] = act[gi * 8 + lane];
    }
    __syncwarp();

    int pidx[9];
    {
        int y = (lane < 25) ? lane / 5 : 0, x = (lane < 25) ? lane % 5 : 0;
        #pragma unroll
        for (int ky = 0; ky < 3; ky++)
            #pragma unroll
            for (int kx = 0; kx < 3; kx++) {
                int yy = y + ky - 1, xx = x + kx - 1;
                pidx[ky*3+kx] = (yy >= 0 && yy < 5 && xx >= 0 && xx < 5) ? yy*5+xx : -1;
            }
    }

    if (lane < 25) {
        float p1[27];
        #pragma unroll
        for (int ic = 0; ic < 3; ic++)
            #pragma unroll
            for (int j = 0; j < 9; j++)
                p1[ic*9+j] = (pidx[j] >= 0) ? s_img[w][ic*25 + pidx[j]] : 0.f;
        #pragma unroll 4
        for (int oc = 0; oc < 32; oc++) {
            float a = __ldg(&c1b[oc]);
            #pragma unroll
            for (int k = 0; k < 27; k++) a += p1[k] * __ldg(&c1w[oc*27+k]);
            s_h1[oc*25+lane] = fmaxf(a, 0.f);
        }
    }
    __syncwarp();

    if (lane < 25) {
        unsigned long long acc2[32];
        #pragma unroll
        for (int q = 0; q < 32; q++) acc2[q] = 0ull;
        for (int ic = 0; ic < 32; ic++) {
            const float* hp = s_h1 + ic * 25;
            unsigned long long p2[9];
            #pragma unroll
            for (int j = 0; j < 9; j++)
                p2[j] = pk2((pidx[j] >= 0) ? hp[pidx[j]] : 0.f);
            const ulonglong2* wt = reinterpret_cast<const ulonglong2*>(&g_c2wt[ic * 576]);
            #pragma unroll
            for (int k = 0; k < 9; k++) {
                #pragma unroll
                for (int q = 0; q < 16; q++) {
                    ulonglong2 wv = __ldg(&wt[k*16 + q]);
                    fma2(acc2[q*2],   p2[k], wv.x);
                    fma2(acc2[q*2+1], p2[k], wv.y);
                }
            }
        }
        #pragma unroll
        for (int q = 0; q < 32; q++) {
            float2 v = upk2(acc2[q]);
            s_h2[w][(2*q)*25   + lane] = fmaxf(v.x + __ldg(&c2b[2*q]),   0.f);
            s_h2[w][(2*q+1)*25 + lane] = fmaxf(v.y + __ldg(&c2b[2*q+1]), 0.f);
        }
    }
    __syncthreads();

    for (int ot = 0; ot < 4; ot++) {
        float acc = 0.f;
        for (int kt = 0; kt < 13; kt++) {
            int k0 = kt * 128, klen = (kt == 12) ? 64 : 128;
            __syncthreads();
            for (int idx = tid; idx < 32 * klen; idx += 128) {
                int r = idx / klen, k = idx - r * klen;
                s_wt[r*132 + k] = encw[(ot*32 + r)*1600 + k0 + k];
            }
            __syncthreads();
            const float4* wt4 = reinterpret_cast<const float4*>(&s_wt[lane*132]);
            const float4* h4  = reinterpret_cast<const float4*>(&s_h2[w][k0]);
            int n4 = klen >> 2;
            #pragma unroll 8
            for (int q = 0; q < n4; q++) {
                float4 wv = wt4[q], hv = h4[q];
                acc += wv.x*hv.x + wv.y*hv.y + wv.z*hv.z + wv.w*hv.w;
            }
        }
        s_x[w][ot*32 + lane] = acc + __ldg(&encb[ot*32 + lane]);
    }

    for (int ot = 0; ot < 16; ot++) {
        __syncthreads();
        for (int idx = tid; idx < 32 * 136; idx += 128) {
            int r = idx / 136, k = idx - r * 136;
            s_wt[r*144 + k] = wih[(ot*32 + r)*136 + k];
        }
        __syncthreads();
        float acc = 0.f;
        const float4* wt4 = reinterpret_cast<const float4*>(&s_wt[lane*144]);
        const float4* xv4 = reinterpret_cast<const float4*>(&s_x[w][0]);
        #pragma unroll 17
        for (int q = 0; q < 34; q++) {
            float4 wv = wt4[q], xv = xv4[q];
            acc += wv.x*xv.x + wv.y*xv.y + wv.z*xv.z + wv.w*xv.w;
        }
        if (valid) {
            int o = ot*32 + lane;
            g_xp[gi*512 + o] = acc + __ldg(&bih[o]) + __ldg(&bhh[o]);
        }
    }
}

// ================= LSTM: HFMA2 matvec, thread-per-gate-row =================
// Thread o (0..511) owns gate-row o: 128 f16 weights register-resident as
// 64 half2. h broadcast from smem as f16x2 via uint4 loads. Gate assignment
// is warp-uniform (warps 0-3:i, 4-7:f, 8-11:g, 12-15:o) -> no shuffles.
// f16 accumulation confined to 4 chunks of 16 HFMA2, widened to f32.
__global__ void __launch_bounds__(512) lstm_kernel(
    const float* __restrict__ whh, float* __restrict__ d_out, int B, int out_size)
{
    __shared__ __align__(16) __half s_h[2][128];
    __shared__ float s_act[512];

    int tid = threadIdx.x;
    int gate = tid >> 7;                 // 0:i 1:f 2:g 3:o (warp-uniform)
    int row = tid & 127;

    // load + quantize this row's weights (once)
    __half2 w2[64];
    {
        const float4* rw = reinterpret_cast<const float4*>(&whh[tid * 128]);
        #pragma unroll
        for (int j = 0; j < 32; j++) {
            float4 v = __ldg(&rw[j]);
            w2[2*j]   = __floats2half2_rn(v.x, v.y);
            w2[2*j+1] = __floats2half2_rn(v.z, v.w);
        }
    }
    if (tid < 128) s_h[0][tid] = __float2half_rn(0.f);

    float xp0 = __ldg(&g_xp[tid]);
    float xp1 = (B > 1) ? __ldg(&g_xp[512 + tid]) : 0.f;
    __syncthreads();

    float c = 0.f;   // live in threads 0..127
    for (int t = 0; t < B; t++) {
        const uint4* sh4 = reinterpret_cast<const uint4*>(s_h[t & 1]);

        __half2 hacc[4];
        #pragma unroll
        for (int ch = 0; ch < 4; ch++) {
            unsigned hw[16];
            uint4 q0 = sh4[ch*4+0], q1 = sh4[ch*4+1], q2 = sh4[ch*4+2], q3 = sh4[ch*4+3];
            hw[0]=q0.x; hw[1]=q0.y; hw[2]=q0.z; hw[3]=q0.w;
            hw[4]=q1.x; hw[5]=q1.y; hw[6]=q1.z; hw[7]=q1.w;
            hw[8]=q2.x; hw[9]=q2.y; hw[10]=q2.z; hw[11]=q2.w;
            hw[12]=q3.x; hw[13]=q3.y; hw[14]=q3.z; hw[15]=q3.w;
            __half2 acc = __float2half2_rn(0.f);
            #pragma unroll
            for (int j = 0; j < 16; j++)
                acc = __hfma2(w2[ch*16 + j], u2h2(hw[j]), acc);
            hacc[ch] = acc;
        }
        float2 f0 = __half22float2(hacc[0]);
        float2 f1 = __half22float2(hacc[1]);
        float2 f2 = __half22float2(hacc[2]);
        float2 f3 = __half22float2(hacc[3]);
        float pre = xp0 + ((f0.x + f0.y) + (f1.x + f1.y)) + ((f2.x + f2.y) + (f3.x + f3.y));

        xp0 = xp1;
        if (t + 2 < B) xp1 = __ldg(&g_xp[(t+2)*512 + tid]);

        float a = (gate == 2) ? ftanh(pre) : fsig(pre);   // warp-uniform branch
        s_act[tid] = a;
        __syncthreads();

        if (tid < 128) {
            float gi = a;                      // gate 0 = i
            float gf = s_act[128 + row];
            float gg = s_act[256 + row];
            float go = s_act[384 + row];
            c = fmaf(gf, c, gi * gg);
            float h = go * ftanh(c);
            s_h[(t+1) & 1][row] = __float2half_rn(h);
            g_hs[t*128 + row] = h;
            if (t == B - 1) {
                d_out[out_size - 256 + row] = h;
                d_out[out_size - 128 + row] = c;
            }
        }
        __syncthreads();
    }
}

// ================= decoder (unchanged) =================
__global__ void __launch_bounds__(128) dec_kernel(
    const float* __restrict__ decw, const float* __restrict__ decb,
    const float* __restrict__ d1b,
    const float* __restrict__ d2w, const float* __restrict__ d2b,
    float* __restrict__ out, int B)
{
    __shared__ float s_hs[4][128];
    __shared__ float s_d[4][1600];
    __shared__ float s_wt[4224];
    __shared__ float s_w2f[864];

    int tid = threadIdx.x, lane = tid & 31, w = tid >> 5;
    int gi = blockIdx.x * 4 + w;
    bool valid = gi < B;

    for (int i = tid; i < 864; i += 128) {
        int ic = i / 27, rem = i % 27, oc = rem / 9, k = rem % 9;
        s_w2f[i] = d2w[(ic*3 + oc)*9 + (8 - k)];
    }
    if (valid)
        for (int i = lane; i < 128; i += 32) s_hs[w][i] = g_hs[gi*128 + i];

    for (int ot = 0; ot < 50; ot++) {
        __syncthreads();
        for (int idx = tid; idx < 4096; idx += 128) {
            int r = idx >> 7, k = idx & 127;
            s_wt[r*132 + k] = decw[(ot*32 + r)*128 + k];
        }
        __syncthreads();
        float acc = 0.f;
        const float4* wt4 = reinterpret_cast<const float4*>(&s_wt[lane*132]);
        const float4* h4  = reinterpret_cast<const float4*>(&s_hs[w][0]);
        #pragma unroll 8
        for (int q = 0; q < 32; q++) {
            float4 wv = wt4[q], hv = h4[q];
            acc += wv.x*hv.x + wv.y*hv.y + wv.z*hv.z + wv.w*hv.w;
        }
        s_d[w][ot*32 + lane] = acc + __ldg(&decb[ot*32 + lane]);
    }
    __syncthreads();

    float* s_h1 = s_wt + w * 800;
    int pidx[9];
    {
        int y = (lane < 25) ? lane / 5 : 0, x = (lane < 25) ? lane % 5 : 0;
        #pragma unroll
        for (int ky = 0; ky < 3; ky++)
            #pragma unroll
            for (int kx = 0; kx < 3; kx++) {
                int yy = y + ky - 1, xx = x + kx - 1;
                pidx[ky*3+kx] = (yy >= 0 && yy < 5 && xx >= 0 && xx < 5) ? yy*5+xx : -1;
            }
    }

    if (lane < 25) {
        unsigned long long acc2[16];
        #pragma unroll
        for (int q = 0; q < 16; q++) acc2[q] = 0ull;
        for (int ic = 0; ic < 64; ic++) {
            const float* dp = &s_d[w][ic * 25];
            unsigned long long p2[9];
            #pragma unroll
            for (int j = 0; j < 9; j++)
                p2[j] = pk2((pidx[j] >= 0) ? dp[pidx[j]] : 0.f);
            const ulonglong2* wt = reinterpret_cast<const ulonglong2*>(&g_d1wt[ic * 288]);
            #pragma unroll
            for (int k = 0; k < 9; k++) {
                #pragma unroll
                for (int q = 0; q < 8; q++) {
                    ulonglong2 wv = __ldg(&wt[k*8 + q]);
                    fma2(acc2[q*2],   p2[k], wv.x);
                    fma2(acc2[q*2+1], p2[k], wv.y);
                }
            }
        }
        #pragma unroll
        for (int q = 0; q < 16; q++) {
            float2 v = upk2(acc2[q]);
            s_h1[(2*q)*25   + lane] = fmaxf(v.x + __ldg(&d1b[2*q]),   0.f);
            s_h1[(2*q+1)*25 + lane] = fmaxf(v.y + __ldg(&d1b[2*q+1]), 0.f);
        }
    }
    __syncwarp();

    if (valid && lane < 25) {
        float acc[3] = {__ldg(&d2b[0]), __ldg(&d2b[1]), __ldg(&d2b[2])};
        for (int ic = 0; ic < 32; ic++) {
            float p[9];
            #pragma unroll
            for (int j = 0; j < 9; j++)
                p[j] = (pidx[j] >= 0) ? s_h1[ic*25 + pidx[j]] : 0.f;
            #pragma unroll
            for (int oc = 0; oc < 3; oc++) {
                float a = acc[oc];
                #pragma unroll
                for (int k = 0; k < 9; k++) a += p[k] * s_w2f[ic*27 + oc*9 + k];
                acc[oc] = a;
            }
        }
        #pragma unroll
        for (int oc = 0; oc < 3; oc++)
            out[gi*75 + oc*25 + lane] = fsig(acc[oc]);
    }
}

extern "C" void kernel_launch(void* const* d_in, const int* in_sizes, int n_in,
                              void* d_out, int out_size)
{
    const float* img   = (const float*)d_in[0];
    const float* act   = (const float*)d_in[1];
    const float* c1w   = (const float*)d_in[2];
    const float* c1b   = (const float*)d_in[3];
    const float* c2w   = (const float*)d_in[4];
    const float* c2b   = (const float*)d_in[5];
    const float* encw  = (const float*)d_in[6];
    const float* encb  = (const float*)d_in[7];
    const float* wih   = (const float*)d_in[8];
    const float* whh   = (const float*)d_in[9];
    const float* bih   = (const float*)d_in[10];
    const float* bhh   = (const float*)d_in[11];
    const float* decw  = (const float*)d_in[12];
    const float* decb  = (const float*)d_in[13];
    const float* d1w   = (const float*)d_in[14];
    const float* d1b   = (const float*)d_in[15];
    const float* d2w   = (const float*)d_in[16];
    const float* d2b   = (const float*)d_in[17];
    float* out = (float*)d_out;

    int B = in_sizes[0] / 75;
    int blocks = (B + 3) / 4;

    prep_kernel<<<72, 256>>>(c2w, d1w);
    enc_kernel<<<blocks, 128>>>(img, act, c1w, c1b, c2b, encw, encb, wih, bih, bhh, B);
    lstm_kernel<<<1, 512>>>(whh, out, B, out_size);
    dec_kernel<<<blocks, 128>>>(decw, decb, d1b, d2w, d2b, out, B);
}

// round 10
// speedup vs baseline: 1.3133x; 1.0122x over previous
#include <cuda_runtime.h>
#include <cuda_fp16.h>
#include <cstdint>

#define BMAX 16384
__device__ float g_xp[BMAX * 512];
__device__ float g_hs[BMAX * 128];
__device__ float g_c2wt[32 * 9 * 64];   // conv2 weights [ic][k][oc]
__device__ float g_d1wt[64 * 9 * 32];   // deconv1 conv-equiv weights [ic][k][oc]

__device__ __forceinline__ float fsig(float x) { return 1.0f / (1.0f + __expf(-x)); }
__device__ __forceinline__ float ftanh(float x) { return 2.0f * fsig(2.0f * x) - 1.0f; }
__device__ __forceinline__ void fma2(unsigned long long& acc, unsigned long long a, unsigned long long b) {
    asm("fma.rn.f32x2 %0, %1, %2, %0;" : "+l"(acc) : "l"(a), "l"(b));
}
__device__ __forceinline__ unsigned long long pk2(float x) {
    unsigned long long r; asm("mov.b64 %0, {%1,%2};" : "=l"(r) : "f"(x), "f"(x)); return r;
}
__device__ __forceinline__ float2 upk2(unsigned long long v) {
    float2 r; asm("mov.b64 {%0,%1}, %2;" : "=f"(r.x), "=f"(r.y) : "l"(v)); return r;
}
__device__ __forceinline__ __half2 u2h2(unsigned u) {
    __half2 h; *reinterpret_cast<unsigned*>(&h) = u; return h;
}

// ================= weight prep =================
__global__ void prep_kernel(const float* __restrict__ c2w, const float* __restrict__ d1w) {
    int i = blockIdx.x * 256 + threadIdx.x;
    if (i < 18432) {
        int oc = i / 288, r = i % 288, ic = r / 9, k = r % 9;
        g_c2wt[(ic * 9 + k) * 64 + oc] = c2w[i];
        int ic2 = i / 288, r2 = i % 288, oc2 = r2 / 9, kk = r2 % 9;
        g_d1wt[(ic2 * 9 + (8 - kk)) * 32 + oc2] = d1w[i];
    }
}

// ================= encoder + input projection (unchanged) =================
__global__ void __launch_bounds__(128) enc_kernel(
    const float* __restrict__ img, const float* __restrict__ act,
    const float* __restrict__ c1w, const float* __restrict__ c1b,
    const float* __restrict__ c2b,
    const float* __restrict__ encw, const float* __restrict__ encb,
    const float* __restrict__ wih, const float* __restrict__ bih,
    const float* __restrict__ bhh, int B)
{
    __shared__ float s_img[4][76];
    __shared__ float s_x[4][136];
    __shared__ float s_h2[4][1600];
    __shared__ float s_wt[4608];

    int tid = threadIdx.x, lane = tid & 31, w = tid >> 5;
    int gi = blockIdx.x * 4 + w;
    bool valid = gi < B;
    float* s_h1 = s_wt + w * 800;

    if (valid) {
        for (int i = lane; i < 75; i += 32) s_img[w][i] = img[gi * 75 + i];
        if (lane < 8) s_x[w][128 + lane] = act[gi * 8 + lane];
    }
    __syncwarp();

    int pidx[9];
    {
        int y = (lane < 25) ? lane / 5 : 0, x = (lane < 25) ? lane % 5 : 0;
        #pragma unroll
        for (int ky = 0; ky < 3; ky++)
            #pragma unroll
            for (int kx = 0; kx < 3; kx++) {
                int yy = y + ky - 1, xx = x + kx - 1;
                pidx[ky*3+kx] = (yy >= 0 && yy < 5 && xx >= 0 && xx < 5) ? yy*5+xx : -1;
            }
    }

    if (lane < 25) {
        float p1[27];
        #pragma unroll
        for (int ic = 0; ic < 3; ic++)
            #pragma unroll
            for (int j = 0; j < 9; j++)
                p1[ic*9+j] = (pidx[j] >= 0) ? s_img[w][ic*25 + pidx[j]] : 0.f;
        #pragma unroll 4
        for (int oc = 0; oc < 32; oc++) {
            float a = __ldg(&c1b[oc]);
            #pragma unroll
            for (int k = 0; k < 27; k++) a += p1[k] * __ldg(&c1w[oc*27+k]);
            s_h1[oc*25+lane] = fmaxf(a, 0.f);
        }
    }
    __syncwarp();

    if (lane < 25) {
        unsigned long long acc2[32];
        #pragma unroll
        for (int q = 0; q < 32; q++) acc2[q] = 0ull;
        for (int ic = 0; ic < 32; ic++) {
            const float* hp = s_h1 + ic * 25;
            unsigned long long p2[9];
            #pragma unroll
            for (int j = 0; j < 9; j++)
                p2[j] = pk2((pidx[j] >= 0) ? hp[pidx[j]] : 0.f);
            const ulonglong2* wt = reinterpret_cast<const ulonglong2*>(&g_c2wt[ic * 576]);
            #pragma unroll
            for (int k = 0; k < 9; k++) {
                #pragma unroll
                for (int q = 0; q < 16; q++) {
                    ulonglong2 wv = __ldg(&wt[k*16 + q]);
                    fma2(acc2[q*2],   p2[k], wv.x);
                    fma2(acc2[q*2+1], p2[k], wv.y);
                }
            }
        }
        #pragma unroll
        for (int q = 0; q < 32; q++) {
            float2 v = upk2(acc2[q]);
            s_h2[w][(2*q)*25   + lane] = fmaxf(v.x + __ldg(&c2b[2*q]),   0.f);
            s_h2[w][(2*q+1)*25 + lane] = fmaxf(v.y + __ldg(&c2b[2*q+1]), 0.f);
        }
    }
    __syncthreads();

    for (int ot = 0; ot < 4; ot++) {
        float acc = 0.f;
        for (int kt = 0; kt < 13; kt++) {
            int k0 = kt * 128, klen = (kt == 12) ? 64 : 128;
            __syncthreads();
            for (int idx = tid; idx < 32 * klen; idx += 128) {
                int r = idx / klen, k = idx - r * klen;
                s_wt[r*132 + k] = encw[(ot*32 + r)*1600 + k0 + k];
            }
            __syncthreads();
            const float4* wt4 = reinterpret_cast<const float4*>(&s_wt[lane*132]);
            const float4* h4  = reinterpret_cast<const float4*>(&s_h2[w][k0]);
            int n4 = klen >> 2;
            #pragma unroll 8
            for (int q = 0; q < n4; q++) {
                float4 wv = wt4[q], hv = h4[q];
                acc += wv.x*hv.x + wv.y*hv.y + wv.z*hv.z + wv.w*hv.w;
            }
        }
        s_x[w][ot*32 + lane] = acc + __ldg(&encb[ot*32 + lane]);
    }

    for (int ot = 0; ot < 16; ot++) {
        __syncthreads();
        for (int idx = tid; idx < 32 * 136; idx += 128) {
            int r = idx / 136, k = idx - r * 136;
            s_wt[r*144 + k] = wih[(ot*32 + r)*136 + k];
        }
        __syncthreads();
        float acc = 0.f;
        const float4* wt4 = reinterpret_cast<const float4*>(&s_wt[lane*144]);
        const float4* xv4 = reinterpret_cast<const float4*>(&s_x[w][0]);
        #pragma unroll 17
        for (int q = 0; q < 34; q++) {
            float4 wv = wt4[q], xv = xv4[q];
            acc += wv.x*xv.x + wv.y*xv.y + wv.z*xv.z + wv.w*xv.w;
        }
        if (valid) {
            int o = ot*32 + lane;
            g_xp[gi*512 + o] = acc + __ldg(&bih[o]) + __ldg(&bhh[o]);
        }
    }
}

// ================= LSTM: HFMA2 matvec, thread-per-gate-row =================
// Launched with grid=148: only block 0 does work (others exit) — probes the
// documented low-grid SM issue throttle that vanishes at grid>=148.
// f16 chunk sums combined by __hadd2 tree (saves ~10 instrs/thread/step).
__global__ void __launch_bounds__(512) lstm_kernel(
    const float* __restrict__ whh, float* __restrict__ d_out, int B, int out_size)
{
    if (blockIdx.x != 0) return;

    __shared__ __align__(16) __half s_h[2][128];
    __shared__ float s_act[512];

    int tid = threadIdx.x;
    int gate = tid >> 7;                 // 0:i 1:f 2:g 3:o (warp-uniform)
    int row = tid & 127;

    // load + quantize this row's weights (once)
    __half2 w2[64];
    {
        const float4* rw = reinterpret_cast<const float4*>(&whh[tid * 128]);
        #pragma unroll
        for (int j = 0; j < 32; j++) {
            float4 v = __ldg(&rw[j]);
            w2[2*j]   = __floats2half2_rn(v.x, v.y);
            w2[2*j+1] = __floats2half2_rn(v.z, v.w);
        }
    }
    if (tid < 128) s_h[0][tid] = __float2half_rn(0.f);

    float xp0 = __ldg(&g_xp[tid]);
    float xp1 = (B > 1) ? __ldg(&g_xp[512 + tid]) : 0.f;
    __syncthreads();

    float c = 0.f;   // live in threads 0..127
    for (int t = 0; t < B; t++) {
        const uint4* sh4 = reinterpret_cast<const uint4*>(s_h[t & 1]);

        __half2 hacc[4];
        #pragma unroll
        for (int ch = 0; ch < 4; ch++) {
            unsigned hw[16];
            uint4 q0 = sh4[ch*4+0], q1 = sh4[ch*4+1], q2 = sh4[ch*4+2], q3 = sh4[ch*4+3];
            hw[0]=q0.x; hw[1]=q0.y; hw[2]=q0.z; hw[3]=q0.w;
            hw[4]=q1.x; hw[5]=q1.y; hw[6]=q1.z; hw[7]=q1.w;
            hw[8]=q2.x; hw[9]=q2.y; hw[10]=q2.z; hw[11]=q2.w;
            hw[12]=q3.x; hw[13]=q3.y; hw[14]=q3.z; hw[15]=q3.w;
            __half2 acc = __float2half2_rn(0.f);
            #pragma unroll
            for (int j = 0; j < 16; j++)
                acc = __hfma2(w2[ch*16 + j], u2h2(hw[j]), acc);
            hacc[ch] = acc;
        }
        // f16 tree combine, single widening
        __half2 s01 = __hadd2(hacc[0], hacc[1]);
        __half2 s23 = __hadd2(hacc[2], hacc[3]);
        float2 fs = __half22float2(__hadd2(s01, s23));
        float pre = xp0 + fs.x + fs.y;

        xp0 = xp1;
        if (t + 2 < B) xp1 = __ldg(&g_xp[(t+2)*512 + tid]);

        float a = (gate == 2) ? ftanh(pre) : fsig(pre);   // warp-uniform branch
        s_act[tid] = a;
        __syncthreads();

        if (tid < 128) {
            float gi = a;                      // gate 0 = i
            float gf = s_act[128 + row];
            float gg = s_act[256 + row];
            float go = s_act[384 + row];
            c = fmaf(gf, c, gi * gg);
            float h = go * ftanh(c);
            s_h[(t+1) & 1][row] = __float2half_rn(h);
            g_hs[t*128 + row] = h;
            if (t == B - 1) {
                d_out[out_size - 256 + row] = h;
                d_out[out_size - 128 + row] = c;
            }
        }
        __syncthreads();
    }
}

// ================= decoder (unchanged) =================
__global__ void __launch_bounds__(128) dec_kernel(
    const float* __restrict__ decw, const float* __restrict__ decb,
    const float* __restrict__ d1b,
    const float* __restrict__ d2w, const float* __restrict__ d2b,
    float* __restrict__ out, int B)
{
    __shared__ float s_hs[4][128];
    __shared__ float s_d[4][1600];
    __shared__ float s_wt[4224];
    __shared__ float s_w2f[864];

    int tid = threadIdx.x, lane = tid & 31, w = tid >> 5;
    int gi = blockIdx.x * 4 + w;
    bool valid = gi < B;

    for (int i = tid; i < 864; i += 128) {
        int ic = i / 27, rem = i % 27, oc = rem / 9, k = rem % 9;
        s_w2f[i] = d2w[(ic*3 + oc)*9 + (8 - k)];
    }
    if (valid)
        for (int i = lane; i < 128; i += 32) s_hs[w][i] = g_hs[gi*128 + i];

    for (int ot = 0; ot < 50; ot++) {
        __syncthreads();
        for (int idx = tid; idx < 4096; idx += 128) {
            int r = idx >> 7, k = idx & 127;
            s_wt[r*132 + k] = decw[(ot*32 + r)*128 + k];
        }
        __syncthreads();
        float acc = 0.f;
        const float4* wt4 = reinterpret_cast<const float4*>(&s_wt[lane*132]);
        const float4* h4  = reinterpret_cast<const float4*>(&s_hs[w][0]);
        #pragma unroll 8
        for (int q = 0; q < 32; q++) {
            float4 wv = wt4[q], hv = h4[q];
            acc += wv.x*hv.x + wv.y*hv.y + wv.z*hv.z + wv.w*hv.w;
        }
        s_d[w][ot*32 + lane] = acc + __ldg(&decb[ot*32 + lane]);
    }
    __syncthreads();

    float* s_h1 = s_wt + w * 800;
    int pidx[9];
    {
        int y = (lane < 25) ? lane / 5 : 0, x = (lane < 25) ? lane % 5 : 0;
        #pragma unroll
        for (int ky = 0; ky < 3; ky++)
            #pragma unroll
            for (int kx = 0; kx < 3; kx++) {
                int yy = y + ky - 1, xx = x + kx - 1;
                pidx[ky*3+kx] = (yy >= 0 && yy < 5 && xx >= 0 && xx < 5) ? yy*5+xx : -1;
            }
    }

    if (lane < 25) {
        unsigned long long acc2[16];
        #pragma unroll
        for (int q = 0; q < 16; q++) acc2[q] = 0ull;
        for (int ic = 0; ic < 64; ic++) {
            const float* dp = &s_d[w][ic * 25];
            unsigned long long p2[9];
            #pragma unroll
            for (int j = 0; j < 9; j++)
                p2[j] = pk2((pidx[j] >= 0) ? dp[pidx[j]] : 0.f);
            const ulonglong2* wt = reinterpret_cast<const ulonglong2*>(&g_d1wt[ic * 288]);
            #pragma unroll
            for (int k = 0; k < 9; k++) {
                #pragma unroll
                for (int q = 0; q < 8; q++) {
                    ulonglong2 wv = __ldg(&wt[k*8 + q]);
                    fma2(acc2[q*2],   p2[k], wv.x);
                    fma2(acc2[q*2+1], p2[k], wv.y);
                }
            }
        }
        #pragma unroll
        for (int q = 0; q < 16; q++) {
            float2 v = upk2(acc2[q]);
            s_h1[(2*q)*25   + lane] = fmaxf(v.x + __ldg(&d1b[2*q]),   0.f);
            s_h1[(2*q+1)*25 + lane] = fmaxf(v.y + __ldg(&d1b[2*q+1]), 0.f);
        }
    }
    __syncwarp();

    if (valid && lane < 25) {
        float acc[3] = {__ldg(&d2b[0]), __ldg(&d2b[1]), __ldg(&d2b[2])};
        for (int ic = 0; ic < 32; ic++) {
            float p[9];
            #pragma unroll
            for (int j = 0; j < 9; j++)
                p[j] = (pidx[j] >= 0) ? s_h1[ic*25 + pidx[j]] : 0.f;
            #pragma unroll
            for (int oc = 0; oc < 3; oc++) {
                float a = acc[oc];
                #pragma unroll
                for (int k = 0; k < 9; k++) a += p[k] * s_w2f[ic*27 + oc*9 + k];
                acc[oc] = a;
            }
        }
        #pragma unroll
        for (int oc = 0; oc < 3; oc++)
            out[gi*75 + oc*25 + lane] = fsig(acc[oc]);
    }
}

extern "C" void kernel_launch(void* const* d_in, const int* in_sizes, int n_in,
                              void* d_out, int out_size)
{
    const float* img   = (const float*)d_in[0];
    const float* act   = (const float*)d_in[1];
    const float* c1w   = (const float*)d_in[2];
    const float* c1b   = (const float*)d_in[3];
    const float* c2w   = (const float*)d_in[4];
    const float* c2b   = (const float*)d_in[5];
    const float* encw  = (const float*)d_in[6];
    const float* encb  = (const float*)d_in[7];
    const float* wih   = (const float*)d_in[8];
    const float* whh   = (const float*)d_in[9];
    const float* bih   = (const float*)d_in[10];
    const float* bhh   = (const float*)d_in[11];
    const float* decw  = (const float*)d_in[12];
    const float* decb  = (const float*)d_in[13];
    const float* d1w   = (const float*)d_in[14];
    const float* d1b   = (const float*)d_in[15];
    const float* d2w   = (const float*)d_in[16];
    const float* d2b   = (const float*)d_in[17];
    float* out = (float*)d_out;

    int B = in_sizes[0] / 75;
    int blocks = (B + 3) / 4;

    prep_kernel<<<72, 256>>>(c2w, d1w);
    enc_kernel<<<blocks, 128>>>(img, act, c1w, c1b, c2b, encw, encb, wih, bih, bhh, B);
    lstm_kernel<<<148, 512>>>(whh, out, B, out_size);   // grid=148: throttle probe, block 0 works
    dec_kernel<<<blocks, 128>>>(decw, decb, d1b, d2w, d2b, out, B);
}

// round 11
// speedup vs baseline: 1.3484x; 1.0267x over previous
#include <cuda_runtime.h>
#include <cuda_fp16.h>
#include <cstdint>

#define BMAX 16384
__device__ float g_xp[BMAX * 512];
__device__ float g_hs[BMAX * 128];
__device__ float g_c2wt[32 * 9 * 64];   // conv2 weights [ic][k][oc]
__device__ float g_d1wt[64 * 9 * 32];   // deconv1 conv-equiv weights [ic][k][oc]

__device__ __forceinline__ float fsig(float x) { return 1.0f / (1.0f + __expf(-x)); }
__device__ __forceinline__ float ftanh(float x) { return 2.0f * fsig(2.0f * x) - 1.0f; }
__device__ __forceinline__ void fma2(unsigned long long& acc, unsigned long long a, unsigned long long b) {
    asm("fma.rn.f32x2 %0, %1, %2, %0;" : "+l"(acc) : "l"(a), "l"(b));
}
__device__ __forceinline__ unsigned long long pk2(float x) {
    unsigned long long r; asm("mov.b64 %0, {%1,%2};" : "=l"(r) : "f"(x), "f"(x)); return r;
}
__device__ __forceinline__ float2 upk2(unsigned long long v) {
    float2 r; asm("mov.b64 {%0,%1}, %2;" : "=f"(r.x), "=f"(r.y) : "l"(v)); return r;
}
__device__ __forceinline__ __half2 u2h2(unsigned u) {
    __half2 h; *reinterpret_cast<unsigned*>(&h) = u; return h;
}

// ================= weight prep =================
__global__ void prep_kernel(const float* __restrict__ c2w, const float* __restrict__ d1w) {
    int i = blockIdx.x * 256 + threadIdx.x;
    if (i < 18432) {
        int oc = i / 288, r = i % 288, ic = r / 9, k = r % 9;
        g_c2wt[(ic * 9 + k) * 64 + oc] = c2w[i];
        int ic2 = i / 288, r2 = i % 288, oc2 = r2 / 9, kk = r2 % 9;
        g_d1wt[(ic2 * 9 + (8 - kk)) * 32 + oc2] = d1w[i];
    }
}

// ================= encoder + input projection (unchanged) =================
__global__ void __launch_bounds__(128) enc_kernel(
    const float* __restrict__ img, const float* __restrict__ act,
    const float* __restrict__ c1w, const float* __restrict__ c1b,
    const float* __restrict__ c2b,
    const float* __restrict__ encw, const float* __restrict__ encb,
    const float* __restrict__ wih, const float* __restrict__ bih,
    const float* __restrict__ bhh, int B)
{
    __shared__ float s_img[4][76];
    __shared__ float s_x[4][136];
    __shared__ float s_h2[4][1600];
    __shared__ float s_wt[4608];

    int tid = threadIdx.x, lane = tid & 31, w = tid >> 5;
    int gi = blockIdx.x * 4 + w;
    bool valid = gi < B;
    float* s_h1 = s_wt + w * 800;

    if (valid) {
        for (int i = lane; i < 75; i += 32) s_img[w][i] = img[gi * 75 + i];
        if (lane < 8) s_x[w][128 + lane] = act[gi * 8 + lane];
    }
    __syncwarp();

    int pidx[9];
    {
        int y = (lane < 25) ? lane / 5 : 0, x = (lane < 25) ? lane % 5 : 0;
        #pragma unroll
        for (int ky = 0; ky < 3; ky++)
            #pragma unroll
            for (int kx = 0; kx < 3; kx++) {
                int yy = y + ky - 1, xx = x + kx - 1;
                pidx[ky*3+kx] = (yy >= 0 && yy < 5 && xx >= 0 && xx < 5) ? yy*5+xx : -1;
            }
    }

    if (lane < 25) {
        float p1[27];
        #pragma unroll
        for (int ic = 0; ic < 3; ic++)
            #pragma unroll
            for (int j = 0; j < 9; j++)
                p1[ic*9+j] = (pidx[j] >= 0) ? s_img[w][ic*25 + pidx[j]] : 0.f;
        #pragma unroll 4
        for (int oc = 0; oc < 32; oc++) {
            float a = __ldg(&c1b[oc]);
            #pragma unroll
            for (int k = 0; k < 27; k++) a += p1[k] * __ldg(&c1w[oc*27+k]);
            s_h1[oc*25+lane] = fmaxf(a, 0.f);
        }
    }
    __syncwarp();

    if (lane < 25) {
        unsigned long long acc2[32];
        #pragma unroll
        for (int q = 0; q < 32; q++) acc2[q] = 0ull;
        for (int ic = 0; ic < 32; ic++) {
            const float* hp = s_h1 + ic * 25;
            unsigned long long p2[9];
            #pragma unroll
            for (int j = 0; j < 9; j++)
                p2[j] = pk2((pidx[j] >= 0) ? hp[pidx[j]] : 0.f);
            const ulonglong2* wt = reinterpret_cast<const ulonglong2*>(&g_c2wt[ic * 576]);
            #pragma unroll
            for (int k = 0; k < 9; k++) {
                #pragma unroll
                for (int q = 0; q < 16; q++) {
                    ulonglong2 wv = __ldg(&wt[k*16 + q]);
                    fma2(acc2[q*2],   p2[k], wv.x);
                    fma2(acc2[q*2+1], p2[k], wv.y);
                }
            }
        }
        #pragma unroll
        for (int q = 0; q < 32; q++) {
            float2 v = upk2(acc2[q]);
            s_h2[w][(2*q)*25   + lane] = fmaxf(v.x + __ldg(&c2b[2*q]),   0.f);
            s_h2[w][(2*q+1)*25 + lane] = fmaxf(v.y + __ldg(&c2b[2*q+1]), 0.f);
        }
    }
    __syncthreads();

    for (int ot = 0; ot < 4; ot++) {
        float acc = 0.f;
        for (int kt = 0; kt < 13; kt++) {
            int k0 = kt * 128, klen = (kt == 12) ? 64 : 128;
            __syncthreads();
            for (int idx = tid; idx < 32 * klen; idx += 128) {
                int r = idx / klen, k = idx - r * klen;
                s_wt[r*132 + k] = encw[(ot*32 + r)*1600 + k0 + k];
            }
            __syncthreads();
            const float4* wt4 = reinterpret_cast<const float4*>(&s_wt[lane*132]);
            const float4* h4  = reinterpret_cast<const float4*>(&s_h2[w][k0]);
            int n4 = klen >> 2;
            #pragma unroll 8
            for (int q = 0; q < n4; q++) {
                float4 wv = wt4[q], hv = h4[q];
                acc += wv.x*hv.x + wv.y*hv.y + wv.z*hv.z + wv.w*hv.w;
            }
        }
        s_x[w][ot*32 + lane] = acc + __ldg(&encb[ot*32 + lane]);
    }

    for (int ot = 0; ot < 16; ot++) {
        __syncthreads();
        for (int idx = tid; idx < 32 * 136; idx += 128) {
            int r = idx / 136, k = idx - r * 136;
            s_wt[r*144 + k] = wih[(ot*32 + r)*136 + k];
        }
        __syncthreads();
        float acc = 0.f;
        const float4* wt4 = reinterpret_cast<const float4*>(&s_wt[lane*144]);
        const float4* xv4 = reinterpret_cast<const float4*>(&s_x[w][0]);
        #pragma unroll 17
        for (int q = 0; q < 34; q++) {
            float4 wv = wt4[q], xv = xv4[q];
            acc += wv.x*xv.x + wv.y*xv.y + wv.z*xv.z + wv.w*xv.w;
        }
        if (valid) {
            int o = ot*32 + lane;
            g_xp[gi*512 + o] = acc + __ldg(&bih[o]) + __ldg(&bhh[o]);
        }
    }
}

// ================= LSTM: HFMA2 matvec, replicated epilogue =================
// Thread tid: gate = tid>>7, row = tid&127, 64 half2 weights in registers.
// Per step: ONE global barrier (s_act exchange, double-buffered) + ONE
// 128-thread named barrier per gate group (group-private s_h copy).
// Epilogue (c,h) replicated in all 4 groups — c is bit-identical, so each
// group feeds its own matvec h-buffer without cross-group coupling.
__global__ void __launch_bounds__(512) lstm_kernel(
    const float* __restrict__ whh, float* __restrict__ d_out, int B, int out_size)
{
    if (blockIdx.x != 0) return;

    __shared__ __align__(16) __half s_h[4][2][128];   // per-group double-buffered h
    __shared__ float s_act[2][512];                   // double-buffered activations

    int tid = threadIdx.x;
    int gate = tid >> 7;                 // 0:i 1:f 2:g 3:o (warp-uniform)
    int row = tid & 127;

    // load + quantize this gate-row's weights (once)
    __half2 w2[64];
    {
        const float4* rw = reinterpret_cast<const float4*>(&whh[tid * 128]);
        #pragma unroll
        for (int j = 0; j < 32; j++) {
            float4 v = __ldg(&rw[j]);
            w2[2*j]   = __floats2half2_rn(v.x, v.y);
            w2[2*j+1] = __floats2half2_rn(v.z, v.w);
        }
    }
    if (tid < 128) {
        __half z = __float2half_rn(0.f);
        #pragma unroll
        for (int g = 0; g < 4; g++) s_h[g][0][tid] = z;
    }

    float xp0 = __ldg(&g_xp[tid]);
    float xp1 = (B > 1) ? __ldg(&g_xp[512 + tid]) : 0.f;
    __syncthreads();

    float c = 0.f;   // replicated: identical in all 4 groups for this row
    for (int t = 0; t < B; t++) {
        // ---- matvec on group-private h buffer ----
        const uint4* sh4 = reinterpret_cast<const uint4*>(s_h[gate][t & 1]);
        __half2 hacc[4];
        #pragma unroll
        for (int ch = 0; ch < 4; ch++) {
            unsigned hw[16];
            uint4 q0 = sh4[ch*4+0], q1 = sh4[ch*4+1], q2 = sh4[ch*4+2], q3 = sh4[ch*4+3];
            hw[0]=q0.x; hw[1]=q0.y; hw[2]=q0.z; hw[3]=q0.w;
            hw[4]=q1.x; hw[5]=q1.y; hw[6]=q1.z; hw[7]=q1.w;
            hw[8]=q2.x; hw[9]=q2.y; hw[10]=q2.z; hw[11]=q2.w;
            hw[12]=q3.x; hw[13]=q3.y; hw[14]=q3.z; hw[15]=q3.w;
            __half2 acc = __float2half2_rn(0.f);
            #pragma unroll
            for (int j = 0; j < 16; j++)
                acc = __hfma2(w2[ch*16 + j], u2h2(hw[j]), acc);
            hacc[ch] = acc;
        }
        __half2 s01 = __hadd2(hacc[0], hacc[1]);
        __half2 s23 = __hadd2(hacc[2], hacc[3]);
        float2 fs = __half22float2(__hadd2(s01, s23));
        float pre = xp0 + fs.x + fs.y;

        xp0 = xp1;
        if (t + 2 < B) xp1 = __ldg(&g_xp[(t+2)*512 + tid]);

        float a = (gate == 2) ? ftanh(pre) : fsig(pre);   // warp-uniform branch
        s_act[t & 1][tid] = a;
        __syncthreads();                                  // global: acts ready

        // ---- replicated epilogue ----
        const float* ab = s_act[t & 1];
        float gi = ab[row];
        float gf = ab[128 + row];
        float gg = ab[256 + row];
        float go = ab[384 + row];
        c = fmaf(gf, c, gi * gg);
        float h = go * ftanh(c);
        s_h[gate][(t + 1) & 1][row] = __float2half_rn(h);
        if (gate == 0) {
            g_hs[t*128 + row] = h;
            if (t == B - 1) {
                d_out[out_size - 256 + row] = h;
                d_out[out_size - 128 + row] = c;
            }
        }
        // group-local barrier: own h buffer ready for next matvec
        asm volatile("bar.sync %0, 128;" :: "r"(gate + 1) : "memory");
    }
}

// ================= decoder (unchanged) =================
__global__ void __launch_bounds__(128) dec_kernel(
    const float* __restrict__ decw, const float* __restrict__ decb,
    const float* __restrict__ d1b,
    const float* __restrict__ d2w, const float* __restrict__ d2b,
    float* __restrict__ out, int B)
{
    __shared__ float s_hs[4][128];
    __shared__ float s_d[4][1600];
    __shared__ float s_wt[4224];
    __shared__ float s_w2f[864];

    int tid = threadIdx.x, lane = tid & 31, w = tid >> 5;
    int gi = blockIdx.x * 4 + w;
    bool valid = gi < B;

    for (int i = tid; i < 864; i += 128) {
        int ic = i / 27, rem = i % 27, oc = rem / 9, k = rem % 9;
        s_w2f[i] = d2w[(ic*3 + oc)*9 + (8 - k)];
    }
    if (valid)
        for (int i = lane; i < 128; i += 32) s_hs[w][i] = g_hs[gi*128 + i];

    for (int ot = 0; ot < 50; ot++) {
        __syncthreads();
        for (int idx = tid; idx < 4096; idx += 128) {
            int r = idx >> 7, k = idx & 127;
            s_wt[r*132 + k] = decw[(ot*32 + r)*128 + k];
        }
        __syncthreads();
        float acc = 0.f;
        const float4* wt4 = reinterpret_cast<const float4*>(&s_wt[lane*132]);
        const float4* h4  = reinterpret_cast<const float4*>(&s_hs[w][0]);
        #pragma unroll 8
        for (int q = 0; q < 32; q++) {
            float4 wv = wt4[q], hv = h4[q];
            acc += wv.x*hv.x + wv.y*hv.y + wv.z*hv.z + wv.w*hv.w;
        }
        s_d[w][ot*32 + lane] = acc + __ldg(&decb[ot*32 + lane]);
    }
    __syncthreads();

    float* s_h1 = s_wt + w * 800;
    int pidx[9];
    {
        int y = (lane < 25) ? lane / 5 : 0, x = (lane < 25) ? lane % 5 : 0;
        #pragma unroll
        for (int ky = 0; ky < 3; ky++)
            #pragma unroll
            for (int kx = 0; kx < 3; kx++) {
                int yy = y + ky - 1, xx = x + kx - 1;
                pidx[ky*3+kx] = (yy >= 0 && yy < 5 && xx >= 0 && xx < 5) ? yy*5+xx : -1;
            }
    }

    if (lane < 25) {
        unsigned long long acc2[16];
        #pragma unroll
        for (int q = 0; q < 16; q++) acc2[q] = 0ull;
        for (int ic = 0; ic < 64; ic++) {
            const float* dp = &s_d[w][ic * 25];
            unsigned long long p2[9];
            #pragma unroll
            for (int j = 0; j < 9; j++)
                p2[j] = pk2((pidx[j] >= 0) ? dp[pidx[j]] : 0.f);
            const ulonglong2* wt = reinterpret_cast<const ulonglong2*>(&g_d1wt[ic * 288]);
            #pragma unroll
            for (int k = 0; k < 9; k++) {
                #pragma unroll
                for (int q = 0; q < 8; q++) {
                    ulonglong2 wv = __ldg(&wt[k*8 + q]);
                    fma2(acc2[q*2],   p2[k], wv.x);
                    fma2(acc2[q*2+1], p2[k], wv.y);
                }
            }
        }
        #pragma unroll
        for (int q = 0; q < 16; q++) {
            float2 v = upk2(acc2[q]);
            s_h1[(2*q)*25   + lane] = fmaxf(v.x + __ldg(&d1b[2*q]),   0.f);
            s_h1[(2*q+1)*25 + lane] = fmaxf(v.y + __ldg(&d1b[2*q+1]), 0.f);
        }
    }
    __syncwarp();

    if (valid && lane < 25) {
        float acc[3] = {__ldg(&d2b[0]), __ldg(&d2b[1]), __ldg(&d2b[2])};
        for (int ic = 0; ic < 32; ic++) {
            float p[9];
            #pragma unroll
            for (int j = 0; j < 9; j++)
                p[j] = (pidx[j] >= 0) ? s_h1[ic*25 + pidx[j]] : 0.f;
            #pragma unroll
            for (int oc = 0; oc < 3; oc++) {
                float a = acc[oc];
                #pragma unroll
                for (int k = 0; k < 9; k++) a += p[k] * s_w2f[ic*27 + oc*9 + k];
                acc[oc] = a;
            }
        }
        #pragma unroll
        for (int oc = 0; oc < 3; oc++)
            out[gi*75 + oc*25 + lane] = fsig(acc[oc]);
    }
}

extern "C" void kernel_launch(void* const* d_in, const int* in_sizes, int n_in,
                              void* d_out, int out_size)
{
    const float* img   = (const float*)d_in[0];
    const float* act   = (const float*)d_in[1];
    const float* c1w   = (const float*)d_in[2];
    const float* c1b   = (const float*)d_in[3];
    const float* c2w   = (const float*)d_in[4];
    const float* c2b   = (const float*)d_in[5];
    const float* encw  = (const float*)d_in[6];
    const float* encb  = (const float*)d_in[7];
    const float* wih   = (const float*)d_in[8];
    const float* whh   = (const float*)d_in[9];
    const float* bih   = (const float*)d_in[10];
    const float* bhh   = (const float*)d_in[11];
    const float* decw  = (const float*)d_in[12];
    const float* decb  = (const float*)d_in[13];
    const float* d1w   = (const float*)d_in[14];
    const float* d1b   = (const float*)d_in[15];
    const float* d2w   = (const float*)d_in[16];
    const float* d2b   = (const float*)d_in[17];
    float* out = (float*)d_out;

    int B = in_sizes[0] / 75;
    int blocks = (B + 3) / 4;

    prep_kernel<<<72, 256>>>(c2w, d1w);
    enc_kernel<<<blocks, 128>>>(img, act, c1w, c1b, c2b, encw, encb, wih, bih, bhh, B);
    lstm_kernel<<<148, 512>>>(whh, out, B, out_size);
    dec_kernel<<<blocks, 128>>>(decw, decb, d1b, d2w, d2b, out, B);
}